// round 3
// baseline (speedup 1.0000x reference)
#include <cuda_runtime.h>

typedef unsigned long long ull;

#define DD    1024
#define LLEN  2048
#define KK    32
#define NSLOT 16
#define HALF_L 1024
#define STEPS (HALF_L / 32)   // 32 iterations per warp

// ---- packed f32x2 helpers (sm_100+ PTX; ptxas never emits these from C++) ----
__device__ __forceinline__ ull f2pack(float lo, float hi) {
    ull r;
    asm("mov.b64 %0, {%1, %2};" : "=l"(r) : "r"(__float_as_uint(lo)), "r"(__float_as_uint(hi)));
    return r;
}
__device__ __forceinline__ void f2unpack(ull v, float& lo, float& hi) {
    unsigned a, b;
    asm("mov.b64 {%0, %1}, %2;" : "=r"(a), "=r"(b) : "l"(v));
    lo = __uint_as_float(a);
    hi = __uint_as_float(b);
}
__device__ __forceinline__ ull f2add(ull a, ull b) {
    ull d; asm("add.rn.f32x2 %0, %1, %2;" : "=l"(d) : "l"(a), "l"(b)); return d;
}
__device__ __forceinline__ ull f2mul(ull a, ull b) {
    ull d; asm("mul.rn.f32x2 %0, %1, %2;" : "=l"(d) : "l"(a), "l"(b)); return d;
}
__device__ __forceinline__ ull f2fma(ull a, ull b, ull c) {
    ull d; asm("fma.rn.f32x2 %0, %1, %2, %3;" : "=l"(d) : "l"(a), "l"(b), "l"(c)); return d;
}

// Two warps per output row d (time-split): warp half h covers l in [h*1024, (h+1)*1024).
// Lane j at step i produces l = h*1024 + 32*i + j:
//   h[d][l] = Re( sum_k w_k ),  w_k = R_k * p_k^(l-1),  step: w_k *= q_k = p_k^32.
// q is warp-uniform so stores stay fully coalesced (128B per warp per step).
__global__ void __launch_bounds__(128) modal_kernel(
    const float* __restrict__ rr, const float* __restrict__ th,
    const float* __restrict__ Rre, const float* __restrict__ Rim,
    const float* __restrict__ h0, float* __restrict__ out)
{
    const int lane  = threadIdx.x & 31;
    const int warp  = blockIdx.x * 4 + (threadIdx.x >> 5);
    const int d     = warp >> 1;
    const int half  = warp & 1;

    const float  INV2PI   = 0.15915494309189535f;
    const float  PI2_HI   = 6.2831854820251465f;     // fp32(2*pi)
    const float  PI2_LO   = -1.7484555e-7f;          // 2*pi - PI2_HI
    const double INV2PI_D = 0.15915494309189535;
    const double TWO_PI_D = 6.283185307179586;

    ull wre[NSLOT], wim[NSLOT], qre[NSLOT], qim[NSLOT];
    const ull M1 = f2pack(-1.0f, -1.0f);             // packed (-1,-1): turns fma into a subtract

    // exponent at step 0 for this lane:  t = half*1024 + lane - 1
    const double e0d = (double)(half * HALF_L + lane - 1);
    const float  e0f = (float)e0d;

    float p_wre = 0.f, p_wim = 0.f, p_qre = 0.f, p_qim = 0.f;

#pragma unroll
    for (int k = 0; k < KK; ++k) {
        const int off = k * DD + d;                  // warp-uniform address -> broadcast load
        float rk = __ldg(rr + off);
        float tk = __ldg(th + off);
        float ar = __ldg(Rre + off);
        float ai = __ldg(Rim + off);
        float lr = __logf(rk);

        // w_k = R_k * p_k^e0.  e0 up to ~1055 -> do the angle product + mod 2pi in double.
        float rad = __expf(e0f * lr);                // underflow to 0 for decayed tails is exact enough
        double angd = e0d * (double)tk;
        double nd = rint(angd * INV2PI_D);
        angd = fma(-nd, TWO_PI_D, angd);
        float ang = (float)angd;
        float s, c;
        __sincosf(ang, &s, &c);
        float cwre = rad * (ar * c - ai * s);
        float cwim = rad * (ar * s + ai * c);

        // q_k = p_k^32   (32*theta exact in fp32; 2-term Cody-Waite reduction)
        float qrad = __expf(32.0f * lr);
        float qa = 32.0f * tk;
        float nq = rintf(qa * INV2PI);
        qa = fmaf(-nq, PI2_HI, qa);
        qa = fmaf(-nq, PI2_LO, qa);
        float qs, qc;
        __sincosf(qa, &qs, &qc);
        float cqre = qrad * qc;
        float cqim = qrad * qs;

        if (k & 1) {
            wre[k >> 1] = f2pack(p_wre, cwre);
            wim[k >> 1] = f2pack(p_wim, cwim);
            qre[k >> 1] = f2pack(p_qre, cqre);
            qim[k >> 1] = f2pack(p_qim, cqim);
        } else {
            p_wre = cwre; p_wim = cwim; p_qre = cqre; p_qim = cqim;
        }
    }

    float* outp = out + (size_t)d * LLEN + half * HALF_L + lane;

#pragma unroll 1
    for (int i = 0; i < STEPS; ++i) {
        // horizontal sum of Re(w): 4 parallel chains of 3 adds, then 3 combining adds
        ull c0 = f2add(wre[0],  wre[1]);  c0 = f2add(c0, wre[2]);  c0 = f2add(c0, wre[3]);
        ull c1 = f2add(wre[4],  wre[5]);  c1 = f2add(c1, wre[6]);  c1 = f2add(c1, wre[7]);
        ull c2 = f2add(wre[8],  wre[9]);  c2 = f2add(c2, wre[10]); c2 = f2add(c2, wre[11]);
        ull c3 = f2add(wre[12], wre[13]); c3 = f2add(c3, wre[14]); c3 = f2add(c3, wre[15]);
        ull t  = f2add(f2add(c0, c1), f2add(c2, c3));
        float lo, hi;
        f2unpack(t, lo, hi);
        outp[i * 32] = lo + hi;                      // coalesced 128B store per warp

        // w *= q : 16 independent packed complex-multiply chains, all on the fma pipe.
        // nr = wre*qre - wim*qim done as fma(t2, -1, t1) to avoid a negated-q register array.
#pragma unroll
        for (int s2 = 0; s2 < NSLOT; ++s2) {
            ull t1 = f2mul(wre[s2], qre[s2]);
            ull t2 = f2mul(wim[s2], qim[s2]);
            ull nr = f2fma(t2, M1, t1);
            ull t3 = f2mul(wre[s2], qim[s2]);
            wim[s2] = f2fma(wim[s2], qre[s2], t3);
            wre[s2] = nr;
        }
    }

    // l == 0 carries h_0 (overwrite the recurrence's l=0 slot)
    if (half == 0 && lane == 0) {
        out[(size_t)d * LLEN] = __ldg(h0 + d);
    }
}

extern "C" void kernel_launch(void* const* d_in, const int* in_sizes, int n_in,
                              void* d_out, int out_size) {
    const float* rr  = (const float*)d_in[0];
    const float* th  = (const float*)d_in[1];
    const float* Rre = (const float*)d_in[2];
    const float* Rim = (const float*)d_in[3];
    const float* h0  = (const float*)d_in[4];
    float* out = (float*)d_out;
    // 2048 warps total: 2 time-halves per d, 4 warps (2 d's) per CTA
    modal_kernel<<<DD * 2 / 4, 128>>>(rr, th, Rre, Rim, h0, out);
}

// round 4
// speedup vs baseline: 2.5682x; 2.5682x over previous
#include <cuda_runtime.h>

typedef unsigned long long ull;

#define DD     1024
#define LLEN   2048
#define KK     32
#define NSLOT  16
#define HALF_L 1024
#define STEPS  (HALF_L / 32)    // 32 time-steps per warp

// ---- packed f32x2 helpers (sm_100+ PTX; ptxas never emits these from C++) ----
__device__ __forceinline__ ull f2pack(float lo, float hi) {
    ull r;
    asm("mov.b64 %0, {%1, %2};" : "=l"(r) : "r"(__float_as_uint(lo)), "r"(__float_as_uint(hi)));
    return r;
}
__device__ __forceinline__ void f2unpack(ull v, float& lo, float& hi) {
    unsigned a, b;
    asm("mov.b64 {%0, %1}, %2;" : "=r"(a), "=r"(b) : "l"(v));
    lo = __uint_as_float(a);
    hi = __uint_as_float(b);
}
__device__ __forceinline__ ull f2add(ull a, ull b) {
    ull d; asm("add.rn.f32x2 %0, %1, %2;" : "=l"(d) : "l"(a), "l"(b)); return d;
}
__device__ __forceinline__ ull f2mul(ull a, ull b) {
    ull d; asm("mul.rn.f32x2 %0, %1, %2;" : "=l"(d) : "l"(a), "l"(b)); return d;
}
__device__ __forceinline__ ull f2fma(ull a, ull b, ull c) {
    ull d; asm("fma.rn.f32x2 %0, %1, %2, %3;" : "=l"(d) : "l"(a), "l"(b), "l"(c)); return d;
}

// x_k[t] = Re(R_k * p_k^t) satisfies the stride-32 second-order real recurrence
//   x[t] = A_k * x[t-32] + B_k * x[t-64],  A_k = 2 r^32 cos(32*theta),  B_k = -r^64
// (p^32 and conj(p)^32 are the roots of z^2 - A z - B). Two warps per row d
// (time halves); lane j at step i emits l = half*1024 + 32*i + j, which carries
// the sum over k of x_k at exponent l-1. 2 fma-pipe ops per packed pole-pair per
// step vs 5 for the complex-multiply form.
__global__ void __launch_bounds__(64) modal_kernel(
    const float* __restrict__ rr, const float* __restrict__ th,
    const float* __restrict__ Rre, const float* __restrict__ Rim,
    const float* __restrict__ h0, float* __restrict__ out)
{
    const int lane = threadIdx.x & 31;
    const int warp = blockIdx.x * 2 + (threadIdx.x >> 5);
    const int d    = warp >> 1;
    const int half = warp & 1;

    const float INV2PI = 0.15915494309189535f;
    const float PI2_HI = 6.2831854820251465f;   // fp32(2*pi)
    const float PI2_LO = -1.7484555e-7f;        // 2*pi - PI2_HI (to ~48 bits total)

    ull x1[NSLOT], x2[NSLOT], A[NSLOT], B[NSLOT];

    // exponents for the two seed states of this lane:
    //   t2 = half*1024 + lane - 33   (older),   t1 = t2 + 32   (newer, first output)
    const float t2f = (float)(half * HALF_L + lane - 33);

    float p_x1 = 0.f, p_x2 = 0.f, p_A = 0.f, p_B = 0.f;

#pragma unroll
    for (int k = 0; k < KK; ++k) {
        const int off = k * DD + d;             // warp-uniform address -> broadcast load
        float rk = __ldg(rr + off);
        float tk = __ldg(th + off);
        float ar = __ldg(Rre + off);
        float ai = __ldg(Rim + off);
        float lr = __logf(rk);

        // ---- recurrence coefficients: A = 2 r^32 cos(32 th), B = -(r^32)^2 ----
        float r32 = __expf(32.0f * lr);         // 32*lr exact scale
        float qa = 32.0f * tk;                  // exact in fp32 (power-of-two scale)
        float nq = rintf(qa * INV2PI);
        qa = fmaf(-nq, PI2_HI, qa);
        qa = fmaf(-nq, PI2_LO, qa);
        float s32, c32;
        __sincosf(qa, &s32, &c32);
        float cA = 2.0f * r32 * c32;
        float cB = -r32 * r32;

        // ---- seed x2 = x(t2):  phase t2*th via exact twoProd + Cody-Waite ----
        float radm = __expf(t2f * lr);
        float ph = t2f * tk;
        float pe = fmaf(t2f, tk, -ph);          // exact low part of the product
        float n2 = rintf(ph * INV2PI);
        float a2 = fmaf(-n2, PI2_HI, ph);
        a2 = a2 + pe;
        a2 = fmaf(-n2, PI2_LO, a2);
        float sm, cm;
        __sincosf(a2, &sm, &cm);
        float cx2 = radm * (ar * cm - ai * sm);

        // ---- seed x1 = x(t2+32): rotate phase by 32*th, scale radius by r^32 ----
        float rad0 = radm * r32;
        float c0 = cm * c32 - sm * s32;
        float s0 = sm * c32 + cm * s32;
        float cx1 = rad0 * (ar * c0 - ai * s0);

        if (k & 1) {
            x1[k >> 1] = f2pack(p_x1, cx1);
            x2[k >> 1] = f2pack(p_x2, cx2);
            A [k >> 1] = f2pack(p_A,  cA);
            B [k >> 1] = f2pack(p_B,  cB);
        } else {
            p_x1 = cx1; p_x2 = cx2; p_A = cA; p_B = cB;
        }
    }

    float* outp = out + (size_t)d * LLEN + half * HALF_L + lane;

    // 2-step unrolled main loop: roles of x1/x2 swap each step (no register moves).
#pragma unroll 1
    for (int i = 0; i < STEPS; i += 2) {
        // emit sum(x1) at l = base + 32*i + lane
        {
            ull c0 = f2add(x1[0],  x1[1]);  c0 = f2add(c0, x1[2]);  c0 = f2add(c0, x1[3]);
            ull c1 = f2add(x1[4],  x1[5]);  c1 = f2add(c1, x1[6]);  c1 = f2add(c1, x1[7]);
            ull c2 = f2add(x1[8],  x1[9]);  c2 = f2add(c2, x1[10]); c2 = f2add(c2, x1[11]);
            ull c3 = f2add(x1[12], x1[13]); c3 = f2add(c3, x1[14]); c3 = f2add(c3, x1[15]);
            ull t  = f2add(f2add(c0, c1), f2add(c2, c3));
            float lo, hi;
            f2unpack(t, lo, hi);
            outp[i * 32] = lo + hi;
        }
        // advance: x2 <- A*x1 + B*x2   (x2 becomes the newest state)
#pragma unroll
        for (int s = 0; s < NSLOT; ++s)
            x2[s] = f2fma(A[s], x1[s], f2mul(B[s], x2[s]));

        // emit sum(x2) at l = base + 32*(i+1) + lane
        {
            ull c0 = f2add(x2[0],  x2[1]);  c0 = f2add(c0, x2[2]);  c0 = f2add(c0, x2[3]);
            ull c1 = f2add(x2[4],  x2[5]);  c1 = f2add(c1, x2[6]);  c1 = f2add(c1, x2[7]);
            ull c2 = f2add(x2[8],  x2[9]);  c2 = f2add(c2, x2[10]); c2 = f2add(c2, x2[11]);
            ull c3 = f2add(x2[12], x2[13]); c3 = f2add(c3, x2[14]); c3 = f2add(c3, x2[15]);
            ull t  = f2add(f2add(c0, c1), f2add(c2, c3));
            float lo, hi;
            f2unpack(t, lo, hi);
            outp[(i + 1) * 32] = lo + hi;
        }
        // advance: x1 <- A*x2 + B*x1
#pragma unroll
        for (int s = 0; s < NSLOT; ++s)
            x1[s] = f2fma(A[s], x2[s], f2mul(B[s], x1[s]));
    }

    // l == 0 carries h_0 (same thread wrote the l=0 slot in iteration 0 -> program order)
    if (half == 0 && lane == 0) {
        out[(size_t)d * LLEN] = __ldg(h0 + d);
    }
}

extern "C" void kernel_launch(void* const* d_in, const int* in_sizes, int n_in,
                              void* d_out, int out_size) {
    const float* rr  = (const float*)d_in[0];
    const float* th  = (const float*)d_in[1];
    const float* Rre = (const float*)d_in[2];
    const float* Rim = (const float*)d_in[3];
    const float* h0  = (const float*)d_in[4];
    float* out = (float*)d_out;
    // 2048 warps: 2 time-halves per d, 2 warps (one d) per 64-thread CTA
    modal_kernel<<<DD, 64>>>(rr, th, Rre, Rim, h0, out);
}

// round 5
// speedup vs baseline: 2.8163x; 1.0966x over previous
#include <cuda_runtime.h>

typedef unsigned long long ull;

#define DD     1024
#define LLEN   2048
#define KK     32
#define KHALF  16
#define NSLOT  8          // 16 poles per warp, packed in pairs
#define HALF_L 1024
#define STEPS  (HALF_L / 32)    // 32 time-steps per warp

// ---- packed f32x2 helpers (sm_100+ PTX; ptxas never emits these from C++) ----
__device__ __forceinline__ ull f2pack(float lo, float hi) {
    ull r;
    asm("mov.b64 %0, {%1, %2};" : "=l"(r) : "r"(__float_as_uint(lo)), "r"(__float_as_uint(hi)));
    return r;
}
__device__ __forceinline__ void f2unpack(ull v, float& lo, float& hi) {
    unsigned a, b;
    asm("mov.b64 {%0, %1}, %2;" : "=r"(a), "=r"(b) : "l"(v));
    lo = __uint_as_float(a);
    hi = __uint_as_float(b);
}
__device__ __forceinline__ ull f2add(ull a, ull b) {
    ull d; asm("add.rn.f32x2 %0, %1, %2;" : "=l"(d) : "l"(a), "l"(b)); return d;
}
__device__ __forceinline__ ull f2mul(ull a, ull b) {
    ull d; asm("mul.rn.f32x2 %0, %1, %2;" : "=l"(d) : "l"(a), "l"(b)); return d;
}
__device__ __forceinline__ ull f2fma(ull a, ull b, ull c) {
    ull d; asm("fma.rn.f32x2 %0, %1, %2, %3;" : "=l"(d) : "l"(a), "l"(b), "l"(c)); return d;
}

__device__ __forceinline__ float reduce8(const ull* x) {
    ull c0 = f2add(x[0], x[1]);  c0 = f2add(c0, x[2]);  c0 = f2add(c0, x[3]);
    ull c1 = f2add(x[4], x[5]);  c1 = f2add(c1, x[6]);  c1 = f2add(c1, x[7]);
    ull t  = f2add(c0, c1);
    float lo, hi;
    f2unpack(t, lo, hi);
    return lo + hi;
}

// x_k[t] = Re(R_k * p_k^t) obeys the stride-32 real recurrence
//   x[t] = A_k x[t-32] + B_k x[t-64],  A_k = 2 r^32 cos(32 th),  B_k = -r^64.
// CTA = 128 threads = 4 warps = one row d:
//   warp w: half = w>>1 (time half), khalf = w&1 (pole half, 16 poles each).
// Lane j at step i emits l = half*1024 + 32*i + j. The two khalf warps of a
// time-half exchange 32-float partial sums through smem (double-buffered, one
// 64-thread named barrier per step) and alternate the add+store duty.
__global__ void __launch_bounds__(128) modal_kernel(
    const float* __restrict__ rr, const float* __restrict__ th,
    const float* __restrict__ Rre, const float* __restrict__ Rim,
    const float* __restrict__ h0, float* __restrict__ out)
{
    __shared__ float buf[4][2][32];               // [warp][slot][lane]

    const int lane  = threadIdx.x & 31;
    const int w     = threadIdx.x >> 5;
    const int half  = w >> 1;
    const int khalf = w & 1;
    const int d     = blockIdx.x;

    const float INV2PI = 0.15915494309189535f;
    const float PI2_HI = 6.2831854820251465f;     // fp32(2*pi)
    const float PI2_LO = -1.7484555e-7f;          // 2*pi - PI2_HI

    ull x1[NSLOT], x2[NSLOT], A[NSLOT], B[NSLOT];

    // seed exponents: t2 = half*1024 + lane - 33 (older), t1 = t2 + 32 (first output)
    const float t2f = (float)(half * HALF_L + lane - 33);

    float p_x1 = 0.f, p_x2 = 0.f, p_A = 0.f, p_B = 0.f;

#pragma unroll
    for (int kk = 0; kk < KHALF; ++kk) {
        const int k   = khalf * KHALF + kk;
        const int off = k * DD + d;               // warp-uniform -> broadcast load
        float rk = __ldg(rr + off);
        float tk = __ldg(th + off);
        float ar = __ldg(Rre + off);
        float ai = __ldg(Rim + off);
        float lr = __logf(rk);

        // A = 2 r^32 cos(32 th), B = -(r^32)^2
        float r32 = __expf(32.0f * lr);
        float qa = 32.0f * tk;                    // exact (power-of-two scale)
        float nq = rintf(qa * INV2PI);
        qa = fmaf(-nq, PI2_HI, qa);
        qa = fmaf(-nq, PI2_LO, qa);
        float s32, c32;
        __sincosf(qa, &s32, &c32);
        float cA = 2.0f * r32 * c32;
        float cB = -r32 * r32;

        // seed x2 = x(t2): phase t2*th via exact twoProd + 2-term Cody-Waite
        float radm = __expf(t2f * lr);
        float ph = t2f * tk;
        float pe = fmaf(t2f, tk, -ph);            // exact low part of product
        float n2 = rintf(ph * INV2PI);
        float a2 = fmaf(-n2, PI2_HI, ph);
        a2 = a2 + pe;
        a2 = fmaf(-n2, PI2_LO, a2);
        float sm, cm;
        __sincosf(a2, &sm, &cm);
        float cx2 = radm * (ar * cm - ai * sm);

        // seed x1 = x(t2+32): rotate by 32th, scale by r^32
        float rad0 = radm * r32;
        float c0 = cm * c32 - sm * s32;
        float s0 = sm * c32 + cm * s32;
        float cx1 = rad0 * (ar * c0 - ai * s0);

        if (kk & 1) {
            x1[kk >> 1] = f2pack(p_x1, cx1);
            x2[kk >> 1] = f2pack(p_x2, cx2);
            A [kk >> 1] = f2pack(p_A,  cA);
            B [kk >> 1] = f2pack(p_B,  cB);
        } else {
            p_x1 = cx1; p_x2 = cx2; p_A = cA; p_B = cB;
        }
    }

    float* outp = out + (size_t)d * LLEN + half * HALF_L;
    const int barid = 1 + half;                   // named barrier per (d, half) pair
    float* myslot0 = &buf[w][0][lane];
    const float* pslot0 = &buf[w ^ 1][0][lane];

#pragma unroll 1
    for (int i = 0; i < STEPS; i += 2) {
        // ---- step i (emit x1, slot 0, khalf==0 stores even steps) ----
        {
            float part = reduce8(x1);
            myslot0[0] = part;                    // STS
            asm volatile("bar.sync %0, 64;" :: "r"(barid) : "memory");
            // advance x2 <- A*x1 + B*x2 (independent of the exchange; fills bar/LDS latency)
#pragma unroll
            for (int s = 0; s < NSLOT; ++s)
                x2[s] = f2fma(A[s], x1[s], f2mul(B[s], x2[s]));
            if (khalf == 0)
                outp[i * 32 + lane] = part + pslot0[0];
        }
        // ---- step i+1 (emit x2, slot 1, khalf==1 stores odd steps) ----
        {
            float part = reduce8(x2);
            myslot0[32] = part;                   // STS slot 1
            asm volatile("bar.sync %0, 64;" :: "r"(barid) : "memory");
#pragma unroll
            for (int s = 0; s < NSLOT; ++s)
                x1[s] = f2fma(A[s], x2[s], f2mul(B[s], x1[s]));
            if (khalf == 1)
                outp[(i + 1) * 32 + lane] = part + pslot0[32];
        }
    }

    // l == 0 carries h_0; same thread (half0/khalf0/lane0) stored l=0 above -> program order
    if (w == 0 && lane == 0) {
        out[(size_t)d * LLEN] = __ldg(h0 + d);
    }
}

extern "C" void kernel_launch(void* const* d_in, const int* in_sizes, int n_in,
                              void* d_out, int out_size) {
    const float* rr  = (const float*)d_in[0];
    const float* th  = (const float*)d_in[1];
    const float* Rre = (const float*)d_in[2];
    const float* Rim = (const float*)d_in[3];
    const float* h0  = (const float*)d_in[4];
    float* out = (float*)d_out;
    // 4096 warps: one d per 128-thread CTA (2 time-halves x 2 pole-halves)
    modal_kernel<<<DD, 128>>>(rr, th, Rre, Rim, h0, out);
}

// round 6
// speedup vs baseline: 2.8270x; 1.0038x over previous
#include <cuda_runtime.h>

typedef unsigned long long ull;

#define DD     1024
#define LLEN   2048
#define KK     32
#define KHALF  16
#define NSLOT  8            // 16 poles per lane, packed in pairs
#define QLEN   512          // time-quarter per warp
#define SREC   16           // recurrence stride = time points per warp-step
#define STEPS  (QLEN / SREC)    // 32 steps

// ---- packed f32x2 helpers (sm_100+ PTX; ptxas never emits these from C++) ----
__device__ __forceinline__ ull f2pack(float lo, float hi) {
    ull r;
    asm("mov.b64 %0, {%1, %2};" : "=l"(r) : "r"(__float_as_uint(lo)), "r"(__float_as_uint(hi)));
    return r;
}
__device__ __forceinline__ void f2unpack(ull v, float& lo, float& hi) {
    unsigned a, b;
    asm("mov.b64 {%0, %1}, %2;" : "=r"(a), "=r"(b) : "l"(v));
    lo = __uint_as_float(a);
    hi = __uint_as_float(b);
}
__device__ __forceinline__ ull f2add(ull a, ull b) {
    ull d; asm("add.rn.f32x2 %0, %1, %2;" : "=l"(d) : "l"(a), "l"(b)); return d;
}
__device__ __forceinline__ ull f2mul(ull a, ull b) {
    ull d; asm("mul.rn.f32x2 %0, %1, %2;" : "=l"(d) : "l"(a), "l"(b)); return d;
}
__device__ __forceinline__ ull f2fma(ull a, ull b, ull c) {
    ull d; asm("fma.rn.f32x2 %0, %1, %2, %3;" : "=l"(d) : "l"(a), "l"(b), "l"(c)); return d;
}

__device__ __forceinline__ float reduce8(const ull* x) {
    ull c0 = f2add(x[0], x[1]);  c0 = f2add(c0, x[2]);  c0 = f2add(c0, x[3]);
    ull c1 = f2add(x[4], x[5]);  c1 = f2add(c1, x[6]);  c1 = f2add(c1, x[7]);
    ull t  = f2add(c0, c1);
    float lo, hi;
    f2unpack(t, lo, hi);
    return lo + hi;
}

// x_k[t] = Re(R_k p_k^t) obeys the stride-16 real recurrence
//   x[t] = A_k x[t-16] + B_k x[t-32],  A_k = 2 r^16 cos(16 th),  B_k = -r^32.
// One warp = one (row d, time-quarter). Lane layout: tsub = lane&15 is a time
// offset, kh = lane>>4 picks 16 of the 32 pole-pairs. At step i lane (kh,tsub)
// holds sum over its 16 poles of x at exponent quarter*512 + 16*i + tsub - 1;
// a single shfl.xor(16) + add merges the two pole halves, lanes<16 store
// l = quarter*512 + 16*i + tsub. No smem, no barriers, warps fully independent.
__global__ void __launch_bounds__(128) modal_kernel(
    const float* __restrict__ rr, const float* __restrict__ th,
    const float* __restrict__ Rre, const float* __restrict__ Rim,
    const float* __restrict__ h0, float* __restrict__ out)
{
    const int lane    = threadIdx.x & 31;
    const int quarter = threadIdx.x >> 5;         // 4 warps per CTA = 4 quarters
    const int d       = blockIdx.x;
    const int tsub    = lane & 15;
    const int kh      = lane >> 4;

    const float INV2PI = 0.15915494309189535f;
    const float PI2_HI = 6.2831854820251465f;     // fp32(2*pi)
    const float PI2_LO = -1.7484555e-7f;          // 2*pi - PI2_HI

    ull x1[NSLOT], x2[NSLOT], A[NSLOT], B[NSLOT];

    // newest seed exponent e1 = quarter*512 + tsub - 1; older seed e2 = e1 - 16
    const float t2f = (float)(quarter * QLEN + tsub - 17);

    float p_x1 = 0.f, p_x2 = 0.f, p_A = 0.f, p_B = 0.f;

#pragma unroll
    for (int kk = 0; kk < KHALF; ++kk) {
        const int k   = kh * KHALF + kk;
        const int off = k * DD + d;               // two addresses per warp -> broadcast
        float rk = __ldg(rr + off);
        float tk = __ldg(th + off);
        float ar = __ldg(Rre + off);
        float ai = __ldg(Rim + off);
        float lr = __logf(rk);

        // A = 2 r^16 cos(16 th), B = -(r^16)^2
        float r16 = __expf(16.0f * lr);
        float qa = 16.0f * tk;                    // exact (power-of-two scale)
        float nq = rintf(qa * INV2PI);
        qa = fmaf(-nq, PI2_HI, qa);
        qa = fmaf(-nq, PI2_LO, qa);
        float s16, c16;
        __sincosf(qa, &s16, &c16);
        float cA = 2.0f * r16 * c16;
        float cB = -r16 * r16;

        // seed x2 = x(e2): phase e2*th via exact twoProd + 2-term Cody-Waite
        float radm = __expf(t2f * lr);
        float ph = t2f * tk;
        float pe = fmaf(t2f, tk, -ph);            // exact low part of the product
        float n2 = rintf(ph * INV2PI);
        float a2 = fmaf(-n2, PI2_HI, ph);
        a2 = a2 + pe;
        a2 = fmaf(-n2, PI2_LO, a2);
        float sm, cm;
        __sincosf(a2, &sm, &cm);
        float cx2 = radm * (ar * cm - ai * sm);

        // seed x1 = x(e2+16): rotate phase by 16 th, scale radius by r^16
        float rad0 = radm * r16;
        float c0 = cm * c16 - sm * s16;
        float s0 = sm * c16 + cm * s16;
        float cx1 = rad0 * (ar * c0 - ai * s0);

        if (kk & 1) {
            x1[kk >> 1] = f2pack(p_x1, cx1);
            x2[kk >> 1] = f2pack(p_x2, cx2);
            A [kk >> 1] = f2pack(p_A,  cA);
            B [kk >> 1] = f2pack(p_B,  cB);
        } else {
            p_x1 = cx1; p_x2 = cx2; p_A = cA; p_B = cB;
        }
    }

    float* outp = out + (size_t)d * LLEN + quarter * QLEN + tsub;
    const bool do_store = (kh == 0);

    // 2-step unrolled main loop: x1/x2 swap roles each step (no register moves)
#pragma unroll 1
    for (int i = 0; i < STEPS; i += 2) {
        {
            float part = reduce8(x1);
            float sum = part + __shfl_xor_sync(0xffffffffu, part, 16);
            if (do_store) outp[i * SREC] = sum;
        }
#pragma unroll
        for (int s = 0; s < NSLOT; ++s)
            x2[s] = f2fma(A[s], x1[s], f2mul(B[s], x2[s]));
        {
            float part = reduce8(x2);
            float sum = part + __shfl_xor_sync(0xffffffffu, part, 16);
            if (do_store) outp[(i + 1) * SREC] = sum;
        }
#pragma unroll
        for (int s = 0; s < NSLOT; ++s)
            x1[s] = f2fma(A[s], x2[s], f2mul(B[s], x1[s]));
    }

    // l == 0 carries h_0; the same thread (quarter 0, lane 0) wrote l=0 in the
    // loop above, so this overwrite is ordered by program order.
    if (quarter == 0 && lane == 0) {
        out[(size_t)d * LLEN] = __ldg(h0 + d);
    }
}

extern "C" void kernel_launch(void* const* d_in, const int* in_sizes, int n_in,
                              void* d_out, int out_size) {
    const float* rr  = (const float*)d_in[0];
    const float* th  = (const float*)d_in[1];
    const float* Rre = (const float*)d_in[2];
    const float* Rim = (const float*)d_in[3];
    const float* h0  = (const float*)d_in[4];
    float* out = (float*)d_out;
    // 4096 independent warps: one d per 128-thread CTA, 4 time-quarters inside
    modal_kernel<<<DD, 128>>>(rr, th, Rre, Rim, h0, out);
}